// round 7
// baseline (speedup 1.0000x reference)
#include <cuda_runtime.h>

#define N_NODES 100000
#define N_EDGES 800000
#define DIM     64
#define HEADS   4
#define DH      16

typedef unsigned long long u64;
typedef unsigned int       u32;

// L2-resident scratch (GB300 L2 ~126MB; Q+K+V = 76.8MB)
__device__ float g_Q[N_NODES * DIM];
__device__ float g_K[N_NODES * DIM];
__device__ float g_V[N_NODES * DIM];
__device__ float g_norm[N_NODES * HEADS];

// ---------------------------------------------------------------------------
// Packed fp32x2 FMA (Blackwell FFMA2).
// ---------------------------------------------------------------------------
__device__ __forceinline__ u64 ffma2(u64 a, u64 b, u64 c) {
    u64 d;
    asm("fma.rn.f32x2 %0, %1, %2, %3;" : "=l"(d) : "l"(a), "l"(b), "l"(c));
    return d;
}
__device__ __forceinline__ u64 pack2(float x) {
    u64 r; u32 xi = __float_as_uint(x);
    asm("mov.b64 %0, {%1, %1};" : "=l"(r) : "r"(xi));
    return r;
}

// ---------------------------------------------------------------------------
// Register-blocked QKV GEMM (best measured variant, R4: 75.0us).
// One W matrix per block (blockIdx.y). 256-node tile, 256 threads;
// thread (tx,ty) computes 8 nodes x 8 cols; scalar A LDS broadcast.
// ---------------------------------------------------------------------------
__global__ __launch_bounds__(256, 2) void gemm_qkv(
    const float* __restrict__ E,
    const float* __restrict__ Wq, const float* __restrict__ Wk,
    const float* __restrict__ Wv)
{
    extern __shared__ float sh[];
    float* sE = sh;                // [256][65]
    float* sW = sh + 256 * 65;     // [64][64]

    int t    = threadIdx.x;
    int m    = blockIdx.y;
    int base = blockIdx.x * 256;

    const float4* Wsrc = (m == 0) ? (const float4*)Wq
                       : (m == 1) ? (const float4*)Wk : (const float4*)Wv;
    #pragma unroll
    for (int i = 0; i < 4; i++)
        ((float4*)sW)[t + i * 256] = Wsrc[t + i * 256];

    for (int i = t; i < 4096; i += 256) {
        int r  = i >> 4;
        int c4 = i & 15;
        int node = base + r;
        float4 v = (node < N_NODES) ? ((const float4*)E)[node * 16 + c4]
                                    : make_float4(0.f, 0.f, 0.f, 0.f);
        float* d = &sE[r * 65 + c4 * 4];
        d[0] = v.x; d[1] = v.y; d[2] = v.z; d[3] = v.w;
    }
    __syncthreads();

    int tx = t & 7, ty = t >> 3;
    int c0 = tx * 8;
    int n0 = ty * 8;

    u64 acc[8][4];
    #pragma unroll
    for (int i = 0; i < 8; i++)
        #pragma unroll
        for (int j = 0; j < 4; j++) acc[i][j] = 0ull;

    #pragma unroll 4
    for (int k = 0; k < 64; k++) {
        ulonglong2 b0 = *(const ulonglong2*)&sW[k * 64 + c0];
        ulonglong2 b1 = *(const ulonglong2*)&sW[k * 64 + c0 + 4];
        #pragma unroll
        for (int i = 0; i < 8; i++) {
            u64 a2 = pack2(sE[(n0 + i) * 65 + k]);
            acc[i][0] = ffma2(a2, b0.x, acc[i][0]);
            acc[i][1] = ffma2(a2, b0.y, acc[i][1]);
            acc[i][2] = ffma2(a2, b1.x, acc[i][2]);
            acc[i][3] = ffma2(a2, b1.y, acc[i][3]);
        }
    }

    float* O = (m == 0) ? g_Q : (m == 1) ? g_K : g_V;
    #pragma unroll
    for (int i = 0; i < 8; i++) {
        int node = base + n0 + i;
        if (node < N_NODES) {
            float4* o = (float4*)(O + node * 64 + c0);
            u64 a0 = acc[i][0], a1 = acc[i][1];
            u64 a2 = acc[i][2], a3 = acc[i][3];
            o[0] = make_float4(__uint_as_float((u32)a0),
                               __uint_as_float((u32)(a0 >> 32)),
                               __uint_as_float((u32)a1),
                               __uint_as_float((u32)(a1 >> 32)));
            o[1] = make_float4(__uint_as_float((u32)a2),
                               __uint_as_float((u32)(a2 >> 32)),
                               __uint_as_float((u32)a3),
                               __uint_as_float((u32)(a3 >> 32)));
        }
    }
}

// ---------------------------------------------------------------------------
// Vector reduction (no return): 1 L2 transaction for 4 floats.
// ---------------------------------------------------------------------------
__device__ __forceinline__ void red_add_v4(float* addr, float a, float b,
                                           float c, float d) {
    asm volatile("red.global.add.v4.f32 [%0], {%1, %2, %3, %4};"
                 :: "l"(addr), "f"(a), "f"(b), "f"(c), "f"(d)
                 : "memory");
}

// ---------------------------------------------------------------------------
// FUSED edge pass: thread per (edge, head).
//   ex = exp(clip(q.k));  att[idx] = ex (unnormalized, fixed later);
//   norm[r,h] += ex;      res[r, h*16..] += ex * V[c, h*16..]
// Valid because res = segsum(ex*v)/norm — division distributes over the
// segment sum (norm constant per (r,h)).
// ---------------------------------------------------------------------------
__global__ void edge_fused(const int* __restrict__ rows, const int* __restrict__ cols,
                           float* __restrict__ res, float* __restrict__ att) {
    int idx = blockIdx.x * blockDim.x + threadIdx.x;
    if (idx >= N_EDGES * HEADS) return;
    int e = idx >> 2, h = idx & 3;
    int r = rows[e], c = cols[e];

    const float4* q = (const float4*)(g_Q + r * DIM + h * DH);
    const float4* k = (const float4*)(g_K + c * DIM + h * DH);
    const float4* v = (const float4*)(g_V + c * DIM + h * DH);

    float4 vv[4];
    #pragma unroll
    for (int i = 0; i < 4; i++) vv[i] = v[i];     // independent, early issue

    float s = 0.0f;
    #pragma unroll
    for (int i = 0; i < 4; i++) {
        float4 a = q[i], b = k[i];
        s += a.x * b.x + a.y * b.y + a.z * b.z + a.w * b.w;
    }
    s = fminf(fmaxf(s, -10.0f), 10.0f);
    float ex = __expf(s);

    att[idx] = ex;
    atomicAdd(&g_norm[r * HEADS + h], ex);

    float* dst = res + r * DIM + h * DH;
    #pragma unroll
    for (int i = 0; i < 4; i++)
        red_add_v4(dst + i * 4, ex * vv[i].x, ex * vv[i].y,
                   ex * vv[i].z, ex * vv[i].w);
}

// ---------------------------------------------------------------------------
// Finalize att: att[idx] /= (norm[rows[e], h] + eps). Streaming + hot gather.
// ---------------------------------------------------------------------------
__global__ void att_finalize(const int* __restrict__ rows, float* __restrict__ att) {
    int idx = blockIdx.x * blockDim.x + threadIdx.x;
    if (idx >= N_EDGES * HEADS) return;
    int e = idx >> 2, h = idx & 3;
    float nm = g_norm[rows[e] * HEADS + h];
    att[idx] = att[idx] / (nm + 1e-8f);
}

// ---------------------------------------------------------------------------
// Finalize res: res[n, c] /= (norm[n, c/16] + eps). Thread per float4 chunk.
// ---------------------------------------------------------------------------
__global__ void res_finalize(float* __restrict__ res) {
    int idx = blockIdx.x * blockDim.x + threadIdx.x;   // [0, N_NODES*16)
    if (idx >= N_NODES * 16) return;
    int n = idx >> 4, chunk = idx & 15;
    int h = chunk >> 2;
    float inv = 1.0f / (g_norm[n * HEADS + h] + 1e-8f);
    float4* p = (float4*)res + idx;
    float4 v = *p;
    v.x *= inv; v.y *= inv; v.z *= inv; v.w *= inv;
    *p = v;
}

// ---------------------------------------------------------------------------
extern "C" void kernel_launch(void* const* d_in, const int* in_sizes, int n_in,
                              void* d_out, int out_size) {
    const float* embeds = (const float*)d_in[0];
    const float* Wq     = (const float*)d_in[1];
    const float* Wk     = (const float*)d_in[2];
    const float* Wv     = (const float*)d_in[3];
    const int*   rows   = (const int*)d_in[4];
    const int*   cols   = (const int*)d_in[5];

    float* res = (float*)d_out;                    // [N_NODES, 64]
    float* att = (float*)d_out + N_NODES * DIM;    // [N_EDGES, 4]

    // 1) zero res + norm
    void* pNorm;
    cudaGetSymbolAddress(&pNorm, g_norm);
    cudaMemsetAsync(res, 0, (size_t)N_NODES * DIM * sizeof(float));
    cudaMemsetAsync(pNorm, 0, (size_t)N_NODES * HEADS * sizeof(float));

    // 2) register-blocked QKV projection (best measured variant)
    const int smem_bytes = (256 * 65 + 64 * 64) * sizeof(float);   // 82944
    cudaFuncSetAttribute(gemm_qkv, cudaFuncAttributeMaxDynamicSharedMemorySize,
                         smem_bytes);
    dim3 gg((N_NODES + 255) / 256, 3);
    gemm_qkv<<<gg, 256, smem_bytes>>>(embeds, Wq, Wk, Wv);

    // 3) fused logits + norm + unnormalized res scatter
    int edge_blocks = (N_EDGES * HEADS + 255) / 256;
    edge_fused<<<edge_blocks, 256>>>(rows, cols, res, att);

    // 4) cheap finalize passes
    att_finalize<<<edge_blocks, 256>>>(rows, att);
    res_finalize<<<(N_NODES * 16 + 255) / 256, 256>>>(res);
}

// round 8
// speedup vs baseline: 1.1584x; 1.1584x over previous
#include <cuda_runtime.h>

#define N_NODES 100000
#define N_EDGES 800000
#define DIM     64
#define HEADS   4
#define DH      16
#define NBLK    ((N_NODES + 255) / 256)   // 391 scan blocks

typedef unsigned long long u64;
typedef unsigned int       u32;

// L2-resident scratch (GB300 L2 ~126MB; Q+K+V = 76.8MB)
__device__ float g_Q[N_NODES * DIM];
__device__ float g_K[N_NODES * DIM];
__device__ float g_V[N_NODES * DIM];

// CSR scratch
__device__ int g_deg[N_NODES];
__device__ int g_start[N_NODES];
__device__ int g_cursor[N_NODES];
__device__ int g_incl[NBLK * 256];
__device__ int g_bsum[NBLK];
__device__ int g_btop[NBLK];
__device__ int g_colS[N_EDGES];
__device__ int g_perm[N_EDGES];

// ---------------------------------------------------------------------------
// Packed fp32x2 FMA (Blackwell FFMA2).
// ---------------------------------------------------------------------------
__device__ __forceinline__ u64 ffma2(u64 a, u64 b, u64 c) {
    u64 d;
    asm("fma.rn.f32x2 %0, %1, %2, %3;" : "=l"(d) : "l"(a), "l"(b), "l"(c));
    return d;
}
__device__ __forceinline__ u64 pack2(float x) {
    u64 r; u32 xi = __float_as_uint(x);
    asm("mov.b64 %0, {%1, %1};" : "=l"(r) : "r"(xi));
    return r;
}

// ---------------------------------------------------------------------------
// Register-blocked QKV GEMM (best measured variant: 75.0us).
// ---------------------------------------------------------------------------
__global__ __launch_bounds__(256, 2) void gemm_qkv(
    const float* __restrict__ E,
    const float* __restrict__ Wq, const float* __restrict__ Wk,
    const float* __restrict__ Wv)
{
    extern __shared__ float sh[];
    float* sE = sh;                // [256][65]
    float* sW = sh + 256 * 65;     // [64][64]

    int t    = threadIdx.x;
    int m    = blockIdx.y;
    int base = blockIdx.x * 256;

    const float4* Wsrc = (m == 0) ? (const float4*)Wq
                       : (m == 1) ? (const float4*)Wk : (const float4*)Wv;
    #pragma unroll
    for (int i = 0; i < 4; i++)
        ((float4*)sW)[t + i * 256] = Wsrc[t + i * 256];

    for (int i = t; i < 4096; i += 256) {
        int r  = i >> 4;
        int c4 = i & 15;
        int node = base + r;
        float4 v = (node < N_NODES) ? ((const float4*)E)[node * 16 + c4]
                                    : make_float4(0.f, 0.f, 0.f, 0.f);
        float* d = &sE[r * 65 + c4 * 4];
        d[0] = v.x; d[1] = v.y; d[2] = v.z; d[3] = v.w;
    }
    __syncthreads();

    int tx = t & 7, ty = t >> 3;
    int c0 = tx * 8;
    int n0 = ty * 8;

    u64 acc[8][4];
    #pragma unroll
    for (int i = 0; i < 8; i++)
        #pragma unroll
        for (int j = 0; j < 4; j++) acc[i][j] = 0ull;

    #pragma unroll 4
    for (int k = 0; k < 64; k++) {
        ulonglong2 b0 = *(const ulonglong2*)&sW[k * 64 + c0];
        ulonglong2 b1 = *(const ulonglong2*)&sW[k * 64 + c0 + 4];
        #pragma unroll
        for (int i = 0; i < 8; i++) {
            u64 a2 = pack2(sE[(n0 + i) * 65 + k]);
            acc[i][0] = ffma2(a2, b0.x, acc[i][0]);
            acc[i][1] = ffma2(a2, b0.y, acc[i][1]);
            acc[i][2] = ffma2(a2, b1.x, acc[i][2]);
            acc[i][3] = ffma2(a2, b1.y, acc[i][3]);
        }
    }

    float* O = (m == 0) ? g_Q : (m == 1) ? g_K : g_V;
    #pragma unroll
    for (int i = 0; i < 8; i++) {
        int node = base + n0 + i;
        if (node < N_NODES) {
            float4* o = (float4*)(O + node * 64 + c0);
            u64 a0 = acc[i][0], a1 = acc[i][1];
            u64 a2 = acc[i][2], a3 = acc[i][3];
            o[0] = make_float4(__uint_as_float((u32)a0),
                               __uint_as_float((u32)(a0 >> 32)),
                               __uint_as_float((u32)a1),
                               __uint_as_float((u32)(a1 >> 32)));
            o[1] = make_float4(__uint_as_float((u32)a2),
                               __uint_as_float((u32)(a2 >> 32)),
                               __uint_as_float((u32)a3),
                               __uint_as_float((u32)(a3 >> 32)));
        }
    }
}

// ---------------------------------------------------------------------------
// CSR build: histogram -> block scan -> top scan -> fix+cursor -> scatter.
// ---------------------------------------------------------------------------
__global__ void hist_kernel(const int* __restrict__ rows) {
    int e = blockIdx.x * blockDim.x + threadIdx.x;
    if (e < N_EDGES) atomicAdd(&g_deg[rows[e]], 1);
}

__global__ void scan_blocks() {
    int i    = blockIdx.x * 256 + threadIdx.x;
    int lane = threadIdx.x & 31, wid = threadIdx.x >> 5;
    int v = (i < N_NODES) ? g_deg[i] : 0;
    #pragma unroll
    for (int o = 1; o < 32; o <<= 1) {
        int u = __shfl_up_sync(0xffffffffu, v, o);
        if (lane >= o) v += u;
    }
    __shared__ int ws[8];
    if (lane == 31) ws[wid] = v;
    __syncthreads();
    if (wid == 0 && lane < 8) {
        int w = ws[lane];
        #pragma unroll
        for (int o = 1; o < 8; o <<= 1) {
            int u = __shfl_up_sync(0xffu, w, o);
            if (lane >= o) w += u;
        }
        ws[lane] = w;
    }
    __syncthreads();
    if (wid > 0) v += ws[wid - 1];
    g_incl[blockIdx.x * 256 + threadIdx.x] = v;
    if (threadIdx.x == 255) g_bsum[blockIdx.x] = v;
}

__global__ void scan_top() {   // 1 block, 512 threads, scans NBLK (391) sums
    int t    = threadIdx.x;
    int lane = t & 31, wid = t >> 5;
    int v = (t < NBLK) ? g_bsum[t] : 0;
    #pragma unroll
    for (int o = 1; o < 32; o <<= 1) {
        int u = __shfl_up_sync(0xffffffffu, v, o);
        if (lane >= o) v += u;
    }
    __shared__ int ws[16];
    if (lane == 31) ws[wid] = v;
    __syncthreads();
    if (wid == 0 && lane < 16) {
        int w = ws[lane];
        #pragma unroll
        for (int o = 1; o < 16; o <<= 1) {
            int u = __shfl_up_sync(0xffffu, w, o);
            if (lane >= o) w += u;
        }
        ws[lane] = w;
    }
    __syncthreads();
    if (wid > 0) v += ws[wid - 1];
    if (t < NBLK) g_btop[t] = v;   // inclusive
}

__global__ void scan_fix() {
    int i = blockIdx.x * 256 + threadIdx.x;
    if (i >= N_NODES) return;
    int boff = (blockIdx.x > 0) ? g_btop[blockIdx.x - 1] : 0;
    int st = g_incl[i] + boff - g_deg[i];    // exclusive start
    g_start[i]  = st;
    g_cursor[i] = st;
}

__global__ void scatter_kernel(const int* __restrict__ rows,
                               const int* __restrict__ cols) {
    int e = blockIdx.x * blockDim.x + threadIdx.x;
    if (e >= N_EDGES) return;
    int r = rows[e];
    int p = atomicAdd(&g_cursor[r], 1);
    g_colS[p] = cols[e];
    g_perm[p] = e;
}

// ---------------------------------------------------------------------------
// Warp-per-node fused attention. Lane l owns dims [2l, 2l+1] (head = l>>3).
// Per edge: coalesced 256B K/V row loads, 8-lane shfl dot, exp, register
// accumulation of norm + res. att staged unnormalized, fixed in-warp.
// ---------------------------------------------------------------------------
__device__ __forceinline__ float edge_ex(float2 q2, int c, int lane, float2& v2) {
    float2 k2 = *(const float2*)&g_K[c * DIM + lane * 2];
    v2        = *(const float2*)&g_V[c * DIM + lane * 2];
    float p = q2.x * k2.x + q2.y * k2.y;
    p += __shfl_xor_sync(0xffffffffu, p, 1);
    p += __shfl_xor_sync(0xffffffffu, p, 2);
    p += __shfl_xor_sync(0xffffffffu, p, 4);
    p = fminf(fmaxf(p, -10.0f), 10.0f);
    return __expf(p);
}

__global__ __launch_bounds__(256) void node_attn(float* __restrict__ res,
                                                 float* __restrict__ att) {
    int gwarp = (blockIdx.x * blockDim.x + threadIdx.x) >> 5;
    if (gwarp >= N_NODES) return;
    int lane = threadIdx.x & 31;
    int n = gwarp;
    int s = g_start[n];
    int d = g_deg[n];
    int end = s + d;

    float2 q2 = *(const float2*)&g_Q[n * DIM + lane * 2];
    float acc0 = 0.f, acc1 = 0.f, norm = 0.f;
    int h = lane >> 3;
    bool leader = (lane & 7) == 0;

    int j = s;
    for (; j + 1 < end; j += 2) {          // 2-edge unroll for load MLP
        int c0 = g_colS[j], c1 = g_colS[j + 1];
        int e0 = g_perm[j], e1 = g_perm[j + 1];
        float2 v0, v1;
        float ex0 = edge_ex(q2, c0, lane, v0);
        float ex1 = edge_ex(q2, c1, lane, v1);
        norm += ex0 + ex1;
        acc0 = fmaf(ex0, v0.x, acc0); acc0 = fmaf(ex1, v1.x, acc0);
        acc1 = fmaf(ex0, v0.y, acc1); acc1 = fmaf(ex1, v1.y, acc1);
        if (leader) {
            att[e0 * 4 + h] = ex0;
            att[e1 * 4 + h] = ex1;
        }
    }
    if (j < end) {
        int c0 = g_colS[j], e0 = g_perm[j];
        float2 v0;
        float ex0 = edge_ex(q2, c0, lane, v0);
        norm += ex0;
        acc0 = fmaf(ex0, v0.x, acc0);
        acc1 = fmaf(ex0, v0.y, acc1);
        if (leader) att[e0 * 4 + h] = ex0;
    }

    float inv = 1.0f / (norm + 1e-8f);
    float2 r2 = make_float2(acc0 * inv, acc1 * inv);
    *(float2*)&res[n * DIM + lane * 2] = r2;

    // normalize this node's att entries (written above by this warp)
    __syncwarp();
    float i0 = __shfl_sync(0xffffffffu, inv, 0);
    float i1 = __shfl_sync(0xffffffffu, inv, 8);
    float i2 = __shfl_sync(0xffffffffu, inv, 16);
    float i3 = __shfl_sync(0xffffffffu, inv, 24);
    for (int jj = s + lane; jj < end; jj += 32) {
        int e = g_perm[jj];
        float4 a = *(float4*)&att[e * 4];
        a.x *= i0; a.y *= i1; a.z *= i2; a.w *= i3;
        *(float4*)&att[e * 4] = a;
    }
}

// ---------------------------------------------------------------------------
extern "C" void kernel_launch(void* const* d_in, const int* in_sizes, int n_in,
                              void* d_out, int out_size) {
    const float* embeds = (const float*)d_in[0];
    const float* Wq     = (const float*)d_in[1];
    const float* Wk     = (const float*)d_in[2];
    const float* Wv     = (const float*)d_in[3];
    const int*   rows   = (const int*)d_in[4];
    const int*   cols   = (const int*)d_in[5];

    float* res = (float*)d_out;                    // [N_NODES, 64]
    float* att = (float*)d_out + N_NODES * DIM;    // [N_EDGES, 4]

    void* pDeg;
    cudaGetSymbolAddress(&pDeg, g_deg);
    cudaMemsetAsync(pDeg, 0, (size_t)N_NODES * sizeof(int));

    // QKV projection
    const int smem_bytes = (256 * 65 + 64 * 64) * sizeof(float);
    cudaFuncSetAttribute(gemm_qkv, cudaFuncAttributeMaxDynamicSharedMemorySize,
                         smem_bytes);
    dim3 gg((N_NODES + 255) / 256, 3);
    gemm_qkv<<<gg, 256, smem_bytes>>>(embeds, Wq, Wk, Wv);

    // CSR build
    int eb = (N_EDGES + 255) / 256;
    hist_kernel<<<eb, 256>>>(rows);
    scan_blocks<<<NBLK, 256>>>();
    scan_top<<<1, 512>>>();
    scan_fix<<<NBLK, 256>>>();
    scatter_kernel<<<eb, 256>>>(rows, cols);

    // fused attention: logits + softmax + aggregate + att normalize
    int nb = (N_NODES * 32 + 255) / 256;
    node_attn<<<nb, 256>>>(res, att);
}

// round 9
// speedup vs baseline: 1.1994x; 1.0354x over previous
#include <cuda_runtime.h>

#define N_NODES 100000
#define N_EDGES 800000
#define DIM     64
#define HEADS   4
#define DH      16
#define NBLK    ((N_NODES + 255) / 256)   // 391 scan blocks

typedef unsigned long long u64;
typedef unsigned int       u32;

// L2-resident scratch (GB300 L2 ~126MB; Q+K+V = 76.8MB)
__device__ float g_Q[N_NODES * DIM];
__device__ float g_K[N_NODES * DIM];
__device__ float g_V[N_NODES * DIM];

// CSR scratch
__device__ int g_deg[N_NODES];
__device__ int g_start[N_NODES];
__device__ int g_cursor[N_NODES];
__device__ int g_incl[NBLK * 256];
__device__ int g_bsum[NBLK];
__device__ int g_btop[NBLK];
__device__ int g_colS[N_EDGES];
__device__ int g_perm[N_EDGES];

// ---------------------------------------------------------------------------
// Packed fp32x2 FMA (Blackwell FFMA2).
// ---------------------------------------------------------------------------
__device__ __forceinline__ u64 ffma2(u64 a, u64 b, u64 c) {
    u64 d;
    asm("fma.rn.f32x2 %0, %1, %2, %3;" : "=l"(d) : "l"(a), "l"(b), "l"(c));
    return d;
}
__device__ __forceinline__ u64 pack2(float x) {
    u64 r; u32 xi = __float_as_uint(x);
    asm("mov.b64 %0, {%1, %1};" : "=l"(r) : "r"(xi));
    return r;
}

// ---------------------------------------------------------------------------
// Register-blocked QKV GEMM (best measured variant: 75.0us).
// ---------------------------------------------------------------------------
__global__ __launch_bounds__(256, 2) void gemm_qkv(
    const float* __restrict__ E,
    const float* __restrict__ Wq, const float* __restrict__ Wk,
    const float* __restrict__ Wv)
{
    extern __shared__ float sh[];
    float* sE = sh;                // [256][65]
    float* sW = sh + 256 * 65;     // [64][64]

    int t    = threadIdx.x;
    int m    = blockIdx.y;
    int base = blockIdx.x * 256;

    const float4* Wsrc = (m == 0) ? (const float4*)Wq
                       : (m == 1) ? (const float4*)Wk : (const float4*)Wv;
    #pragma unroll
    for (int i = 0; i < 4; i++)
        ((float4*)sW)[t + i * 256] = Wsrc[t + i * 256];

    for (int i = t; i < 4096; i += 256) {
        int r  = i >> 4;
        int c4 = i & 15;
        int node = base + r;
        float4 v = (node < N_NODES) ? ((const float4*)E)[node * 16 + c4]
                                    : make_float4(0.f, 0.f, 0.f, 0.f);
        float* d = &sE[r * 65 + c4 * 4];
        d[0] = v.x; d[1] = v.y; d[2] = v.z; d[3] = v.w;
    }
    __syncthreads();

    int tx = t & 7, ty = t >> 3;
    int c0 = tx * 8;
    int n0 = ty * 8;

    u64 acc[8][4];
    #pragma unroll
    for (int i = 0; i < 8; i++)
        #pragma unroll
        for (int j = 0; j < 4; j++) acc[i][j] = 0ull;

    #pragma unroll 4
    for (int k = 0; k < 64; k++) {
        ulonglong2 b0 = *(const ulonglong2*)&sW[k * 64 + c0];
        ulonglong2 b1 = *(const ulonglong2*)&sW[k * 64 + c0 + 4];
        #pragma unroll
        for (int i = 0; i < 8; i++) {
            u64 a2 = pack2(sE[(n0 + i) * 65 + k]);
            acc[i][0] = ffma2(a2, b0.x, acc[i][0]);
            acc[i][1] = ffma2(a2, b0.y, acc[i][1]);
            acc[i][2] = ffma2(a2, b1.x, acc[i][2]);
            acc[i][3] = ffma2(a2, b1.y, acc[i][3]);
        }
    }

    float* O = (m == 0) ? g_Q : (m == 1) ? g_K : g_V;
    #pragma unroll
    for (int i = 0; i < 8; i++) {
        int node = base + n0 + i;
        if (node < N_NODES) {
            float4* o = (float4*)(O + node * 64 + c0);
            u64 a0 = acc[i][0], a1 = acc[i][1];
            u64 a2 = acc[i][2], a3 = acc[i][3];
            o[0] = make_float4(__uint_as_float((u32)a0),
                               __uint_as_float((u32)(a0 >> 32)),
                               __uint_as_float((u32)a1),
                               __uint_as_float((u32)(a1 >> 32)));
            o[1] = make_float4(__uint_as_float((u32)a2),
                               __uint_as_float((u32)(a2 >> 32)),
                               __uint_as_float((u32)a3),
                               __uint_as_float((u32)(a3 >> 32)));
        }
    }
}

// ---------------------------------------------------------------------------
// CSR build: histogram -> block scan -> top scan -> fix+cursor -> scatter.
// ---------------------------------------------------------------------------
__global__ void hist_kernel(const int* __restrict__ rows) {
    int e = blockIdx.x * blockDim.x + threadIdx.x;
    if (e < N_EDGES) atomicAdd(&g_deg[rows[e]], 1);
}

__global__ void scan_blocks() {
    int i    = blockIdx.x * 256 + threadIdx.x;
    int lane = threadIdx.x & 31, wid = threadIdx.x >> 5;
    int v = (i < N_NODES) ? g_deg[i] : 0;
    #pragma unroll
    for (int o = 1; o < 32; o <<= 1) {
        int u = __shfl_up_sync(0xffffffffu, v, o);
        if (lane >= o) v += u;
    }
    __shared__ int ws[8];
    if (lane == 31) ws[wid] = v;
    __syncthreads();
    if (wid == 0 && lane < 8) {
        int w = ws[lane];
        #pragma unroll
        for (int o = 1; o < 8; o <<= 1) {
            int u = __shfl_up_sync(0xffu, w, o);
            if (lane >= o) w += u;
        }
        ws[lane] = w;
    }
    __syncthreads();
    if (wid > 0) v += ws[wid - 1];
    g_incl[blockIdx.x * 256 + threadIdx.x] = v;
    if (threadIdx.x == 255) g_bsum[blockIdx.x] = v;
}

__global__ void scan_top() {   // 1 block, 512 threads, scans NBLK (391) sums
    int t    = threadIdx.x;
    int lane = t & 31, wid = t >> 5;
    int v = (t < NBLK) ? g_bsum[t] : 0;
    #pragma unroll
    for (int o = 1; o < 32; o <<= 1) {
        int u = __shfl_up_sync(0xffffffffu, v, o);
        if (lane >= o) v += u;
    }
    __shared__ int ws[16];
    if (lane == 31) ws[wid] = v;
    __syncthreads();
    if (wid == 0 && lane < 16) {
        int w = ws[lane];
        #pragma unroll
        for (int o = 1; o < 16; o <<= 1) {
            int u = __shfl_up_sync(0xffffu, w, o);
            if (lane >= o) w += u;
        }
        ws[lane] = w;
    }
    __syncthreads();
    if (wid > 0) v += ws[wid - 1];
    if (t < NBLK) g_btop[t] = v;   // inclusive
}

__global__ void scan_fix() {
    int i = blockIdx.x * 256 + threadIdx.x;
    if (i >= N_NODES) return;
    int boff = (blockIdx.x > 0) ? g_btop[blockIdx.x - 1] : 0;
    int st = g_incl[i] + boff - g_deg[i];    // exclusive start
    g_start[i]  = st;
    g_cursor[i] = st;
}

__global__ void scatter_kernel(const int* __restrict__ rows,
                               const int* __restrict__ cols) {
    int e = blockIdx.x * blockDim.x + threadIdx.x;
    if (e >= N_EDGES) return;
    int r = rows[e];
    int p = atomicAdd(&g_cursor[r], 1);
    g_colS[p] = cols[e];
    g_perm[p] = e;
}

// ---------------------------------------------------------------------------
// Warp-per-node fused attention. Lane l owns dims [2l, 2l+1] (head = l>>3).
// 4-edge unroll: 8 independent 8B loads in flight before the shfl chains.
// ---------------------------------------------------------------------------
__device__ __forceinline__ float edge_ex(float2 q2, int c, int lane, float2& v2) {
    float2 k2 = *(const float2*)&g_K[c * DIM + lane * 2];
    v2        = *(const float2*)&g_V[c * DIM + lane * 2];
    float p = q2.x * k2.x + q2.y * k2.y;
    p += __shfl_xor_sync(0xffffffffu, p, 1);
    p += __shfl_xor_sync(0xffffffffu, p, 2);
    p += __shfl_xor_sync(0xffffffffu, p, 4);
    p = fminf(fmaxf(p, -10.0f), 10.0f);
    return __expf(p);
}

__global__ __launch_bounds__(256) void node_attn(float* __restrict__ res,
                                                 float* __restrict__ att) {
    int gwarp = (blockIdx.x * blockDim.x + threadIdx.x) >> 5;
    if (gwarp >= N_NODES) return;
    int lane = threadIdx.x & 31;
    int n = gwarp;
    int s = g_start[n];
    int d = g_deg[n];
    int end = s + d;

    float2 q2 = *(const float2*)&g_Q[n * DIM + lane * 2];
    float acc0 = 0.f, acc1 = 0.f, norm = 0.f;
    int h = lane >> 3;
    bool leader = (lane & 7) == 0;

    int j = s;
    for (; j + 3 < end; j += 4) {
        int c0 = g_colS[j],     c1 = g_colS[j + 1];
        int c2 = g_colS[j + 2], c3 = g_colS[j + 3];
        int e0 = g_perm[j],     e1 = g_perm[j + 1];
        int e2 = g_perm[j + 2], e3 = g_perm[j + 3];
        float2 v0, v1, v2, v3;
        float ex0 = edge_ex(q2, c0, lane, v0);
        float ex1 = edge_ex(q2, c1, lane, v1);
        float ex2 = edge_ex(q2, c2, lane, v2);
        float ex3 = edge_ex(q2, c3, lane, v3);
        norm += (ex0 + ex1) + (ex2 + ex3);
        acc0 = fmaf(ex0, v0.x, acc0); acc0 = fmaf(ex1, v1.x, acc0);
        acc0 = fmaf(ex2, v2.x, acc0); acc0 = fmaf(ex3, v3.x, acc0);
        acc1 = fmaf(ex0, v0.y, acc1); acc1 = fmaf(ex1, v1.y, acc1);
        acc1 = fmaf(ex2, v2.y, acc1); acc1 = fmaf(ex3, v3.y, acc1);
        if (leader) {
            att[e0 * 4 + h] = ex0;
            att[e1 * 4 + h] = ex1;
            att[e2 * 4 + h] = ex2;
            att[e3 * 4 + h] = ex3;
        }
    }
    for (; j < end; j++) {
        int c0 = g_colS[j], e0 = g_perm[j];
        float2 v0;
        float ex0 = edge_ex(q2, c0, lane, v0);
        norm += ex0;
        acc0 = fmaf(ex0, v0.x, acc0);
        acc1 = fmaf(ex0, v0.y, acc1);
        if (leader) att[e0 * 4 + h] = ex0;
    }

    float inv = 1.0f / (norm + 1e-8f);
    float2 r2 = make_float2(acc0 * inv, acc1 * inv);
    *(float2*)&res[n * DIM + lane * 2] = r2;

    // normalize this node's att entries (written above by this warp)
    __syncwarp();
    float i0 = __shfl_sync(0xffffffffu, inv, 0);
    float i1 = __shfl_sync(0xffffffffu, inv, 8);
    float i2 = __shfl_sync(0xffffffffu, inv, 16);
    float i3 = __shfl_sync(0xffffffffu, inv, 24);
    for (int jj = s + lane; jj < end; jj += 32) {
        int e = g_perm[jj];
        float4 a = *(float4*)&att[e * 4];
        a.x *= i0; a.y *= i1; a.z *= i2; a.w *= i3;
        *(float4*)&att[e * 4] = a;
    }
}

// ---------------------------------------------------------------------------
extern "C" void kernel_launch(void* const* d_in, const int* in_sizes, int n_in,
                              void* d_out, int out_size) {
    const float* embeds = (const float*)d_in[0];
    const float* Wq     = (const float*)d_in[1];
    const float* Wk     = (const float*)d_in[2];
    const float* Wv     = (const float*)d_in[3];
    const int*   rows   = (const int*)d_in[4];
    const int*   cols   = (const int*)d_in[5];

    float* res = (float*)d_out;                    // [N_NODES, 64]
    float* att = (float*)d_out + N_NODES * DIM;    // [N_EDGES, 4]

    // One-time host-side resources (no device memory; identical work per call)
    static cudaStream_t sCsr = nullptr;
    static cudaEvent_t  evFork = nullptr, evJoin = nullptr;
    if (sCsr == nullptr) {
        cudaStreamCreateWithFlags(&sCsr, cudaStreamNonBlocking);
        cudaEventCreateWithFlags(&evFork, cudaEventDisableTiming);
        cudaEventCreateWithFlags(&evJoin, cudaEventDisableTiming);
    }

    void* pDeg;
    cudaGetSymbolAddress(&pDeg, g_deg);

    // Fork: CSR chain (depends only on rows/cols) runs parallel to the GEMM.
    cudaEventRecord(evFork, 0);
    cudaStreamWaitEvent(sCsr, evFork, 0);

    // Branch A (stream 0): QKV projection
    const int smem_bytes = (256 * 65 + 64 * 64) * sizeof(float);
    cudaFuncSetAttribute(gemm_qkv, cudaFuncAttributeMaxDynamicSharedMemorySize,
                         smem_bytes);
    dim3 gg((N_NODES + 255) / 256, 3);
    gemm_qkv<<<gg, 256, smem_bytes>>>(embeds, Wq, Wk, Wv);

    // Branch B (sCsr): CSR build
    int eb = (N_EDGES + 255) / 256;
    cudaMemsetAsync(pDeg, 0, (size_t)N_NODES * sizeof(int), sCsr);
    hist_kernel<<<eb, 256, 0, sCsr>>>(rows);
    scan_blocks<<<NBLK, 256, 0, sCsr>>>();
    scan_top<<<1, 512, 0, sCsr>>>();
    scan_fix<<<NBLK, 256, 0, sCsr>>>();
    scatter_kernel<<<eb, 256, 0, sCsr>>>(rows, cols);

    // Join
    cudaEventRecord(evJoin, sCsr);
    cudaStreamWaitEvent(0, evJoin, 0);

    // fused attention: logits + softmax + aggregate + att normalize
    int nb = (N_NODES * 32 + 255) / 256;
    node_attn<<<nb, 256>>>(res, att);
}

// round 11
// speedup vs baseline: 1.2204x; 1.0175x over previous
#include <cuda_runtime.h>
#include <cuda_bf16.h>
#include <mma.h>

using namespace nvcuda;

#define N_NODES 100000
#define N_PAD   100096                    // 128-aligned for unguarded wmma stores
#define N_EDGES 800000
#define DIM     64
#define HEADS   4
#define NBLK    ((N_NODES + 255) / 256)   // 391 scan blocks

typedef unsigned long long u64;
typedef unsigned int       u32;

// L2-resident scratch (GB300 L2 ~126MB; Q+K+V = 76.9MB)
__device__ float g_Q[N_PAD * DIM];
__device__ float g_K[N_PAD * DIM];
__device__ float g_V[N_PAD * DIM];

// CSR scratch
__device__ int g_deg[N_NODES];
__device__ int g_start[N_NODES];
__device__ int g_cursor[N_NODES];
__device__ int g_incl[NBLK * 256];
__device__ int g_bsum[NBLK];
__device__ int g_btop[NBLK];
__device__ int g_colS[N_EDGES];
__device__ int g_perm[N_EDGES];

// ---------------------------------------------------------------------------
// Tensor-core QKV GEMM via wmma (bf16 two-term split, err ~2^-18).
// Block: 256 threads (8 warps), 128-node tile.
//   A (E tile):  [128][AS] bf16 hi/lo, row-major, AS=72 (16B-mult, depadded)
//   B (W^T):     [64][BS]  bf16 hi/lo, "col_major" frag = B[n][k], BS=72
// Warp w owns m-tile rows [16w,16w+16); loops 4 n-tiles; per k-frag (4):
// 3 mma (hi*hi + hi*lo + lo*hi). Epilogue: direct wmma store (padded global).
// ---------------------------------------------------------------------------
#define AS 72
#define BS 72

__global__ __launch_bounds__(256, 2) void gemm_qkv_wmma(
    const float* __restrict__ E,
    const float* __restrict__ Wq, const float* __restrict__ Wk,
    const float* __restrict__ Wv)
{
    extern __shared__ __nv_bfloat16 sb[];
    __nv_bfloat16* Ah = sb;                    // [128][AS]
    __nv_bfloat16* Al = Ah + 128 * AS;
    __nv_bfloat16* Bh = Al + 128 * AS;         // [64][BS]
    __nv_bfloat16* Bl = Bh + 64 * BS;

    int t    = threadIdx.x;
    int w    = t >> 5;
    int base = blockIdx.x * 128;

    // --- A tile: 256 threads, each converts half a row (32 floats) ---
    {
        int r    = t >> 1;
        int coff = (t & 1) * 32;
        int node = base + r;
        const float2* src = (const float2*)(E + (size_t)node * 64 + coff);
        __nv_bfloat16* dh = Ah + r * AS + coff;
        __nv_bfloat16* dl = Al + r * AS + coff;
        if (node < N_NODES) {
            #pragma unroll
            for (int i = 0; i < 16; i++) {
                float2 x = src[i];
                __nv_bfloat162 h = __float22bfloat162_rn(x);
                float2 hf = __bfloat1622float2(h);
                __nv_bfloat162 l = __float22bfloat162_rn(
                    make_float2(x.x - hf.x, x.y - hf.y));
                *(__nv_bfloat162*)(dh + 2 * i) = h;
                *(__nv_bfloat162*)(dl + 2 * i) = l;
            }
        } else {
            #pragma unroll
            for (int i = 0; i < 16; i++) {
                *(__nv_bfloat162*)(dh + 2 * i) = __nv_bfloat162(0.f, 0.f);
                *(__nv_bfloat162*)(dl + 2 * i) = __nv_bfloat162(0.f, 0.f);
            }
        }
    }

    for (int m = 0; m < 3; m++) {
        const float* W = (m == 0) ? Wq : (m == 1) ? Wk : Wv;
        if (m > 0) __syncthreads();            // protect B reuse

        // --- B tile: B[n][k] = W[k][n], 16 elements per thread ---
        for (int idx = t; idx < 4096; idx += 256) {
            int n = idx >> 6, k = idx & 63;
            float x = W[k * 64 + n];
            __nv_bfloat16 h = __float2bfloat16_rn(x);
            __nv_bfloat16 l = __float2bfloat16_rn(x - __bfloat162float(h));
            Bh[n * BS + k] = h;
            Bl[n * BS + k] = l;
        }
        __syncthreads();

        wmma::fragment<wmma::accumulator, 16, 16, 16, float> acc[4];
        #pragma unroll
        for (int n = 0; n < 4; n++) wmma::fill_fragment(acc[n], 0.0f);

        #pragma unroll
        for (int k = 0; k < 4; k++) {
            wmma::fragment<wmma::matrix_a, 16, 16, 16, __nv_bfloat16,
                           wmma::row_major> ah, al;
            wmma::load_matrix_sync(ah, Ah + (w * 16) * AS + k * 16, AS);
            wmma::load_matrix_sync(al, Al + (w * 16) * AS + k * 16, AS);
            #pragma unroll
            for (int n = 0; n < 4; n++) {
                wmma::fragment<wmma::matrix_b, 16, 16, 16, __nv_bfloat16,
                               wmma::col_major> bh, bl;
                wmma::load_matrix_sync(bh, Bh + (n * 16) * BS + k * 16, BS);
                wmma::load_matrix_sync(bl, Bl + (n * 16) * BS + k * 16, BS);
                wmma::mma_sync(acc[n], ah, bh, acc[n]);
                wmma::mma_sync(acc[n], ah, bl, acc[n]);
                wmma::mma_sync(acc[n], al, bh, acc[n]);
            }
        }

        float* O = (m == 0) ? g_Q : (m == 1) ? g_K : g_V;
        #pragma unroll
        for (int n = 0; n < 4; n++)
            wmma::store_matrix_sync(O + (size_t)(base + w * 16) * 64 + n * 16,
                                    acc[n], 64, wmma::mem_row_major);
    }
}

#define SMEM_WMMA ((2 * 128 * AS + 2 * 64 * BS) * (int)sizeof(__nv_bfloat16))

// ---------------------------------------------------------------------------
// CSR build: histogram -> block scan -> top scan -> fix+cursor -> scatter.
// ---------------------------------------------------------------------------
__global__ void hist_kernel(const int* __restrict__ rows) {
    int e = blockIdx.x * blockDim.x + threadIdx.x;
    if (e < N_EDGES) atomicAdd(&g_deg[rows[e]], 1);
}

__global__ void scan_blocks() {
    int i    = blockIdx.x * 256 + threadIdx.x;
    int lane = threadIdx.x & 31, wid = threadIdx.x >> 5;
    int v = (i < N_NODES) ? g_deg[i] : 0;
    #pragma unroll
    for (int o = 1; o < 32; o <<= 1) {
        int u = __shfl_up_sync(0xffffffffu, v, o);
        if (lane >= o) v += u;
    }
    __shared__ int ws[8];
    if (lane == 31) ws[wid] = v;
    __syncthreads();
    if (wid == 0 && lane < 8) {
        int x = ws[lane];
        #pragma unroll
        for (int o = 1; o < 8; o <<= 1) {
            int u = __shfl_up_sync(0xffu, x, o);
            if (lane >= o) x += u;
        }
        ws[lane] = x;
    }
    __syncthreads();
    if (wid > 0) v += ws[wid - 1];
    g_incl[blockIdx.x * 256 + threadIdx.x] = v;
    if (threadIdx.x == 255) g_bsum[blockIdx.x] = v;
}

__global__ void scan_top() {
    int t    = threadIdx.x;
    int lane = t & 31, wid = t >> 5;
    int v = (t < NBLK) ? g_bsum[t] : 0;
    #pragma unroll
    for (int o = 1; o < 32; o <<= 1) {
        int u = __shfl_up_sync(0xffffffffu, v, o);
        if (lane >= o) v += u;
    }
    __shared__ int ws[16];
    if (lane == 31) ws[wid] = v;
    __syncthreads();
    if (wid == 0 && lane < 16) {
        int x = ws[lane];
        #pragma unroll
        for (int o = 1; o < 16; o <<= 1) {
            int u = __shfl_up_sync(0xffffu, x, o);
            if (lane >= o) x += u;
        }
        ws[lane] = x;
    }
    __syncthreads();
    if (wid > 0) v += ws[wid - 1];
    if (t < NBLK) g_btop[t] = v;
}

__global__ void scan_fix() {
    int i = blockIdx.x * 256 + threadIdx.x;
    if (i >= N_NODES) return;
    int boff = (blockIdx.x > 0) ? g_btop[blockIdx.x - 1] : 0;
    int st = g_incl[i] + boff - g_deg[i];
    g_start[i]  = st;
    g_cursor[i] = st;
}

__global__ void scatter_kernel(const int* __restrict__ rows,
                               const int* __restrict__ cols) {
    int e = blockIdx.x * blockDim.x + threadIdx.x;
    if (e >= N_EDGES) return;
    int r = rows[e];
    int p = atomicAdd(&g_cursor[r], 1);
    g_colS[p] = cols[e];
    g_perm[p] = e;
}

// ---------------------------------------------------------------------------
// Warp-per-node fused attention (R9 best). Lane l owns dims [2l, 2l+1].
// ---------------------------------------------------------------------------
__device__ __forceinline__ float edge_ex(float2 q2, int c, int lane, float2& v2) {
    float2 k2 = *(const float2*)&g_K[c * DIM + lane * 2];
    v2        = *(const float2*)&g_V[c * DIM + lane * 2];
    float p = q2.x * k2.x + q2.y * k2.y;
    p += __shfl_xor_sync(0xffffffffu, p, 1);
    p += __shfl_xor_sync(0xffffffffu, p, 2);
    p += __shfl_xor_sync(0xffffffffu, p, 4);
    p = fminf(fmaxf(p, -10.0f), 10.0f);
    return __expf(p);
}

__global__ __launch_bounds__(256) void node_attn(float* __restrict__ res,
                                                 float* __restrict__ att) {
    int gwarp = (blockIdx.x * blockDim.x + threadIdx.x) >> 5;
    if (gwarp >= N_NODES) return;
    int lane = threadIdx.x & 31;
    int n = gwarp;
    int s = g_start[n];
    int d = g_deg[n];
    int end = s + d;

    float2 q2 = *(const float2*)&g_Q[n * DIM + lane * 2];
    float acc0 = 0.f, acc1 = 0.f, norm = 0.f;
    int h = lane >> 3;
    bool leader = (lane & 7) == 0;

    int j = s;
    for (; j + 3 < end; j += 4) {
        int c0 = g_colS[j],     c1 = g_colS[j + 1];
        int c2 = g_colS[j + 2], c3 = g_colS[j + 3];
        int e0 = g_perm[j],     e1 = g_perm[j + 1];
        int e2 = g_perm[j + 2], e3 = g_perm[j + 3];
        float2 v0, v1, v2, v3;
        float ex0 = edge_ex(q2, c0, lane, v0);
        float ex1 = edge_ex(q2, c1, lane, v1);
        float ex2 = edge_ex(q2, c2, lane, v2);
        float ex3 = edge_ex(q2, c3, lane, v3);
        norm += (ex0 + ex1) + (ex2 + ex3);
        acc0 = fmaf(ex0, v0.x, acc0); acc0 = fmaf(ex1, v1.x, acc0);
        acc0 = fmaf(ex2, v2.x, acc0); acc0 = fmaf(ex3, v3.x, acc0);
        acc1 = fmaf(ex0, v0.y, acc1); acc1 = fmaf(ex1, v1.y, acc1);
        acc1 = fmaf(ex2, v2.y, acc1); acc1 = fmaf(ex3, v3.y, acc1);
        if (leader) {
            att[e0 * 4 + h] = ex0;
            att[e1 * 4 + h] = ex1;
            att[e2 * 4 + h] = ex2;
            att[e3 * 4 + h] = ex3;
        }
    }
    for (; j < end; j++) {
        int c0 = g_colS[j], e0 = g_perm[j];
        float2 v0;
        float ex0 = edge_ex(q2, c0, lane, v0);
        norm += ex0;
        acc0 = fmaf(ex0, v0.x, acc0);
        acc1 = fmaf(ex0, v0.y, acc1);
        if (leader) att[e0 * 4 + h] = ex0;
    }

    float inv = 1.0f / (norm + 1e-8f);
    float2 r2 = make_float2(acc0 * inv, acc1 * inv);
    *(float2*)&res[n * DIM + lane * 2] = r2;

    __syncwarp();
    float i0 = __shfl_sync(0xffffffffu, inv, 0);
    float i1 = __shfl_sync(0xffffffffu, inv, 8);
    float i2 = __shfl_sync(0xffffffffu, inv, 16);
    float i3 = __shfl_sync(0xffffffffu, inv, 24);
    for (int jj = s + lane; jj < end; jj += 32) {
        int e = g_perm[jj];
        float4 a = *(float4*)&att[e * 4];
        a.x *= i0; a.y *= i1; a.z *= i2; a.w *= i3;
        *(float4*)&att[e * 4] = a;
    }
}

// ---------------------------------------------------------------------------
extern "C" void kernel_launch(void* const* d_in, const int* in_sizes, int n_in,
                              void* d_out, int out_size) {
    const float* embeds = (const float*)d_in[0];
    const float* Wq     = (const float*)d_in[1];
    const float* Wk     = (const float*)d_in[2];
    const float* Wv     = (const float*)d_in[3];
    const int*   rows   = (const int*)d_in[4];
    const int*   cols   = (const int*)d_in[5];

    float* res = (float*)d_out;                    // [N_NODES, 64]
    float* att = (float*)d_out + N_NODES * DIM;    // [N_EDGES, 4]

    static cudaStream_t sCsr = nullptr;
    static cudaEvent_t  evFork = nullptr, evJoin = nullptr;
    if (sCsr == nullptr) {
        cudaStreamCreateWithFlags(&sCsr, cudaStreamNonBlocking);
        cudaEventCreateWithFlags(&evFork, cudaEventDisableTiming);
        cudaEventCreateWithFlags(&evJoin, cudaEventDisableTiming);
    }

    void* pDeg;
    cudaGetSymbolAddress(&pDeg, g_deg);

    // Fork: CSR chain (rows/cols only) parallel to tensor-core GEMM.
    cudaEventRecord(evFork, 0);
    cudaStreamWaitEvent(sCsr, evFork, 0);

    // Branch A (stream 0): wmma bf16-split QKV projection
    cudaFuncSetAttribute(gemm_qkv_wmma,
                         cudaFuncAttributeMaxDynamicSharedMemorySize, SMEM_WMMA);
    gemm_qkv_wmma<<<(N_NODES + 127) / 128, 256, SMEM_WMMA>>>(embeds, Wq, Wk, Wv);

    // Branch B (sCsr): CSR build
    int eb = (N_EDGES + 255) / 256;
    cudaMemsetAsync(pDeg, 0, (size_t)N_NODES * sizeof(int), sCsr);
    hist_kernel<<<eb, 256, 0, sCsr>>>(rows);
    scan_blocks<<<NBLK, 256, 0, sCsr>>>();
    scan_top<<<1, 512, 0, sCsr>>>();
    scan_fix<<<NBLK, 256, 0, sCsr>>>();
    scatter_kernel<<<eb, 256, 0, sCsr>>>(rows, cols);

    // Join
    cudaEventRecord(evJoin, sCsr);
    cudaStreamWaitEvent(0, evJoin, 0);

    // fused attention: logits + softmax + aggregate + att normalize
    int nb = (N_NODES * 32 + 255) / 256;
    node_attn<<<nb, 256>>>(res, att);
}